// round 2
// baseline (speedup 1.0000x reference)
#include <cuda_runtime.h>

#define N_NODES 50000
#define N_EDGES 200000
#define IN_F 32
#define HID 32
#define N_GRAPHS 64
#define TILE_E 256

// ---------------- scratch (no allocs allowed) ----------------
__device__ float g_agg[N_NODES * HID];
__device__ float g_cnt[N_NODES];
__device__ float g_gsum[N_GRAPHS * HID];
__device__ float g_gcnt[N_GRAPHS];

__device__ __forceinline__ unsigned f2tf32(float f) {
    unsigned r;
    asm("cvt.rna.tf32.f32 %0, %1;" : "=r"(r) : "f"(f));
    return r;
}

// D = A*B + D
#define MMA_ACC(C, a0, a1, a2, a3, B0, B1)                                      \
    asm volatile("mma.sync.aligned.m16n8k8.row.col.f32.tf32.tf32.f32 "          \
                 "{%0,%1,%2,%3}, {%4,%5,%6,%7}, {%8,%9}, {%0,%1,%2,%3};"        \
                 : "+f"((C)[0]), "+f"((C)[1]), "+f"((C)[2]), "+f"((C)[3])       \
                 : "r"(a0), "r"(a1), "r"(a2), "r"(a3), "r"(B0), "r"(B1))

// D = A*B (zero C)
#define MMA_SET(C, a0, a1, a2, a3, B0, B1)                                      \
    asm volatile("mma.sync.aligned.m16n8k8.row.col.f32.tf32.tf32.f32 "          \
                 "{%0,%1,%2,%3}, {%4,%5,%6,%7}, {%8,%9}, {%10,%11,%12,%13};"    \
                 : "=f"((C)[0]), "=f"((C)[1]), "=f"((C)[2]), "=f"((C)[3])       \
                 : "r"(a0), "r"(a1), "r"(a2), "r"(a3), "r"(B0), "r"(B1),        \
                   "f"(0.f), "f"(0.f), "f"(0.f), "f"(0.f))

// ---------------- K0: zero scratch ----------------
__global__ void zero_kernel() {
    int idx = blockIdx.x * blockDim.x + threadIdx.x;
    int stride = gridDim.x * blockDim.x;
    for (int i = idx; i < N_NODES * HID; i += stride) g_agg[i] = 0.f;
    for (int i = idx; i < N_NODES; i += stride) g_cnt[i] = 0.f;
    if (idx < N_GRAPHS * HID) g_gsum[idx] = 0.f;
    if (idx < N_GRAPHS) g_gcnt[idx] = 0.f;
}

// ---------------- K1: edge messages ----------------
// msg[e, n] = sum_j h(e,j) * (x[src] @ W2_j)[n] + (x[src] @ B)[n]
// Per j: T = X_tile @ W2_j via mma (A = x in tf32, fixed), then fp32 fold
// acc += h_row * T. Bias handled as j=64 slab with h == 1.
//
// smem layout for W2 chunk (4 j-slabs x 32 k-rows x 32 n), arranged so the
// B fragment rows (k, k+4) are an adjacent u32 pair (one LDS.64), with an
// XOR swizzle for conflict-free access:
//   element (slab, krow, n), krow = ic*8 + b, c0p = b&3, hi = b>>2:
//   off_u32 = slab*1024 + (ic*4 + c0p)*64 + ((n ^ (c0p<<2)) << 1) + hi
__global__ void __launch_bounds__(256, 2) edge_kernel(
    const float* __restrict__ x, const int* __restrict__ ei,
    const float* __restrict__ ea,
    const float* __restrict__ w1g, const float* __restrict__ b1g,
    const float* __restrict__ w2, const float* __restrict__ b2)
{
    __shared__ unsigned w2_sm[4096];   // 16 KB chunk
    __shared__ float w1_sm[64], b1_sm[64];

    const int tid  = threadIdx.x;
    const int lane = tid & 31;
    const int wrp  = tid >> 5;
    const int e0   = blockIdx.x * TILE_E;

    if (tid < 64) { w1_sm[tid] = w1g[tid]; b1_sm[tid] = b1g[tid]; }

    const int r0 = lane >> 2;      // 0..7
    const int c0 = lane & 3;       // 0..3

    int   dstv[4];
    bool  val[4];
    float av[4];
    unsigned xtf[4][8];            // tf32 A fragments (x only), fixed

    #pragma unroll
    for (int t = 0; t < 4; t++) {
        int eg = e0 + wrp * 32 + r0 + t * 8;
        val[t] = (eg < N_EDGES);
        int s  = val[t] ? ei[eg] : 0;
        dstv[t] = val[t] ? ei[N_EDGES + eg] : 0;
        av[t]   = val[t] ? ea[eg] : 0.f;
        const float* xr = x + s * IN_F;
        #pragma unroll
        for (int q = 0; q < 8; q++)
            xtf[t][q] = f2tf32(val[t] ? xr[c0 + 4 * q] : 0.f);
    }

    // degree counts: exactly once per edge
    if (c0 == 0) {
        #pragma unroll
        for (int t = 0; t < 4; t++)
            if (val[t]) atomicAdd(&g_cnt[dstv[t]], 1.f);
    }

    // per-thread consumer address bases (swizzled n), in u32 units
    int nbase[4];
    #pragma unroll
    for (int nb = 0; nb < 4; nb++)
        nbase[nb] = ((nb * 8 + r0) ^ (c0 << 2)) << 1;
    const int cbase = c0 * 64;

    float acc[2][4][4];
    #pragma unroll
    for (int a = 0; a < 2; a++)
        #pragma unroll
        for (int b = 0; b < 4; b++)
            #pragma unroll
            for (int c = 0; c < 4; c++) acc[a][b][c] = 0.f;

    for (int jc = 0; jc < 17; jc++) {
        __syncthreads();
        if (jc < 16) {
            const float4* srcp = (const float4*)(w2 + jc * 4096);
            #pragma unroll
            for (int k = 0; k < 4; k++) {
                int f = tid + k * 256;            // float4 id, 0..1023
                int kr = f >> 3;                  // k-row in chunk, 0..127
                int n4 = (f & 7) << 2;
                float4 v = srcp[f];
                int slab = kr >> 5, krow = kr & 31;
                int ic = krow >> 3, b = krow & 7;
                int c0p = b & 3, hi = b >> 2;
                int n4s = n4 ^ (c0p << 2);
                unsigned* p = &w2_sm[slab * 1024 + (ic * 4 + c0p) * 64 + (n4s << 1) + hi];
                p[0] = f2tf32(v.x); p[2] = f2tf32(v.y);
                p[4] = f2tf32(v.z); p[6] = f2tf32(v.w);
            }
        } else {
            // bias slab: 1024 floats = 256 float4s, k-rows 0..31 (slab 0)
            const float4* srcp = (const float4*)b2;
            int f = tid;
            int kr = f >> 3;
            int n4 = (f & 7) << 2;
            float4 v = srcp[f];
            int ic = kr >> 3, b = kr & 7;
            int c0p = b & 3, hi = b >> 2;
            int n4s = n4 ^ (c0p << 2);
            unsigned* p = &w2_sm[(ic * 4 + c0p) * 64 + (n4s << 1) + hi];
            p[0] = f2tf32(v.x); p[2] = f2tf32(v.y);
            p[4] = f2tf32(v.z); p[6] = f2tf32(v.w);
        }
        __syncthreads();

        const int njj = (jc < 16) ? 4 : 1;
        for (int jj = 0; jj < njj; jj++) {
            float h[4];
            if (jc < 16) {
                int j = jc * 4 + jj;
                float wj = w1_sm[j], bj = b1_sm[j];
                #pragma unroll
                for (int t = 0; t < 4; t++)
                    h[t] = fmaxf(fmaf(av[t], wj, bj), 0.f);
            } else {
                h[0] = h[1] = h[2] = h[3] = 1.f;
            }
            const int sbase = jj * 1024 + cbase;
            #pragma unroll
            for (int nb = 0; nb < 4; nb++) {
                uint2 bp[4];
                #pragma unroll
                for (int ic = 0; ic < 4; ic++)
                    bp[ic] = *(const uint2*)&w2_sm[sbase + ic * 256 + nbase[nb]];
                float T0[4], T1[4];
                MMA_SET(T0, xtf[0][0], xtf[1][0], xtf[0][1], xtf[1][1], bp[0].x, bp[0].y);
                MMA_SET(T1, xtf[2][0], xtf[3][0], xtf[2][1], xtf[3][1], bp[0].x, bp[0].y);
                MMA_ACC(T0, xtf[0][2], xtf[1][2], xtf[0][3], xtf[1][3], bp[1].x, bp[1].y);
                MMA_ACC(T1, xtf[2][2], xtf[3][2], xtf[2][3], xtf[3][3], bp[1].x, bp[1].y);
                MMA_ACC(T0, xtf[0][4], xtf[1][4], xtf[0][5], xtf[1][5], bp[2].x, bp[2].y);
                MMA_ACC(T1, xtf[2][4], xtf[3][4], xtf[2][5], xtf[3][5], bp[2].x, bp[2].y);
                MMA_ACC(T0, xtf[0][6], xtf[1][6], xtf[0][7], xtf[1][7], bp[3].x, bp[3].y);
                MMA_ACC(T1, xtf[2][6], xtf[3][6], xtf[2][7], xtf[3][7], bp[3].x, bp[3].y);
                // fold: acc += h_row * T  (rows: T*[0,1]->edge t, T*[2,3]->edge t+1)
                acc[0][nb][0] = fmaf(h[0], T0[0], acc[0][nb][0]);
                acc[0][nb][1] = fmaf(h[0], T0[1], acc[0][nb][1]);
                acc[0][nb][2] = fmaf(h[1], T0[2], acc[0][nb][2]);
                acc[0][nb][3] = fmaf(h[1], T0[3], acc[0][nb][3]);
                acc[1][nb][0] = fmaf(h[2], T1[0], acc[1][nb][0]);
                acc[1][nb][1] = fmaf(h[2], T1[1], acc[1][nb][1]);
                acc[1][nb][2] = fmaf(h[3], T1[2], acc[1][nb][2]);
                acc[1][nb][3] = fmaf(h[3], T1[3], acc[1][nb][3]);
            }
        }
    }

    // scatter messages (segment-sum by dst)
    #pragma unroll
    for (int tt = 0; tt < 2; tt++) {
        int t0 = tt * 2, t1 = tt * 2 + 1;
        #pragma unroll
        for (int nb = 0; nb < 4; nb++) {
            int n = nb * 8 + 2 * c0;
            if (val[t0]) {
                atomicAdd(&g_agg[dstv[t0] * HID + n],     acc[tt][nb][0]);
                atomicAdd(&g_agg[dstv[t0] * HID + n + 1], acc[tt][nb][1]);
            }
            if (val[t1]) {
                atomicAdd(&g_agg[dstv[t1] * HID + n],     acc[tt][nb][2]);
                atomicAdd(&g_agg[dstv[t1] * HID + n + 1], acc[tt][nb][3]);
            }
        }
    }
}

// ---------------- K2: node update + graph pooling ----------------
__global__ void __launch_bounds__(256) node_kernel(
    const float* __restrict__ x, const int* __restrict__ batch,
    const float* __restrict__ root, const float* __restrict__ conv_bias)
{
    int wrp = threadIdx.x >> 5, lane = threadIdx.x & 31;
    int n = blockIdx.x * 8 + wrp;
    if (n >= N_NODES) return;
    float v = g_agg[n * HID + lane];
    float c = g_cnt[n];
    v /= fmaxf(c, 1.f);
    float xv = x[n * IN_F + lane];
    float s = 0.f;
    #pragma unroll
    for (int i = 0; i < IN_F; i++) {
        float xi = __shfl_sync(0xffffffffu, xv, i);
        s = fmaf(xi, root[i * HID + lane], s);
    }
    v = fmaxf(v + s + conv_bias[lane], 0.f);
    int g = batch[n];
    atomicAdd(&g_gsum[g * HID + lane], v);
    if (lane == 0) atomicAdd(&g_gcnt[g], 1.f);
}

// ---------------- K3: classifier ----------------
__global__ void final_kernel(const float* __restrict__ lin_w,
                             const float* __restrict__ lin_b,
                             float* __restrict__ out)
{
    int t = threadIdx.x;
    if (t >= N_GRAPHS * 2) return;
    int g = t >> 1, c = t & 1;
    float cnt = fmaxf(g_gcnt[g], 1.f);
    float s = 0.f;
    #pragma unroll
    for (int h = 0; h < HID; h++)
        s += g_gsum[g * HID + h] * lin_w[h * 2 + c];
    out[g * 2 + c] = s / cnt + lin_b[c];
}

// ---------------- launcher ----------------
extern "C" void kernel_launch(void* const* d_in, const int* in_sizes, int n_in,
                              void* d_out, int out_size) {
    const float* x    = (const float*)d_in[0];
    const int*   ei   = (const int*)  d_in[1];
    const float* ea   = (const float*)d_in[2];
    const int*   bat  = (const int*)  d_in[3];
    const float* w1   = (const float*)d_in[4];
    const float* b1   = (const float*)d_in[5];
    const float* w2   = (const float*)d_in[6];
    const float* b2   = (const float*)d_in[7];
    const float* root = (const float*)d_in[8];
    const float* cb   = (const float*)d_in[9];
    const float* lw   = (const float*)d_in[10];
    const float* lb   = (const float*)d_in[11];
    float* out = (float*)d_out;

    zero_kernel<<<512, 256>>>();
    edge_kernel<<<(N_EDGES + TILE_E - 1) / TILE_E, 256>>>(x, ei, ea, w1, b1, w2, b2);
    node_kernel<<<(N_NODES + 7) / 8, 256>>>(x, bat, root, cb);
    final_kernel<<<1, 128>>>(lw, lb, out);
}

// round 3
// speedup vs baseline: 1.4996x; 1.4996x over previous
#include <cuda_runtime.h>
#include <cuda_fp16.h>

#define N_NODES 50000
#define N_EDGES 200000
#define IN_F 32
#define HID 32
#define N_GRAPHS 64
#define TILE_E 256

// ---------------- scratch (no allocs allowed) ----------------
__device__ float g_agg[N_NODES * HID];
__device__ float g_cnt[N_NODES];
__device__ float g_gsum[N_GRAPHS * HID];
__device__ float g_gcnt[N_GRAPHS];

__device__ __forceinline__ unsigned packh2(float lo, float hi) {
    __half2 h = __floats2half2_rn(lo, hi);
    return *(unsigned*)&h;
}

// fp16 MMA, fp32 accumulate. D = A*B + D
#define MMA16_ACC(C, a0, a1, a2, a3, B0, B1)                                    \
    asm volatile("mma.sync.aligned.m16n8k16.row.col.f32.f16.f16.f32 "           \
                 "{%0,%1,%2,%3}, {%4,%5,%6,%7}, {%8,%9}, {%0,%1,%2,%3};"        \
                 : "+f"((C)[0]), "+f"((C)[1]), "+f"((C)[2]), "+f"((C)[3])       \
                 : "r"(a0), "r"(a1), "r"(a2), "r"(a3), "r"(B0), "r"(B1))

// D = A*B (zero C)
#define MMA16_SET(C, a0, a1, a2, a3, B0, B1)                                    \
    asm volatile("mma.sync.aligned.m16n8k16.row.col.f32.f16.f16.f32 "           \
                 "{%0,%1,%2,%3}, {%4,%5,%6,%7}, {%8,%9}, {%10,%11,%12,%13};"    \
                 : "=f"((C)[0]), "=f"((C)[1]), "=f"((C)[2]), "=f"((C)[3])       \
                 : "r"(a0), "r"(a1), "r"(a2), "r"(a3), "r"(B0), "r"(B1),        \
                   "f"(0.f), "f"(0.f), "f"(0.f), "f"(0.f))

// ---------------- K0: zero scratch ----------------
__global__ void zero_kernel() {
    int idx = blockIdx.x * blockDim.x + threadIdx.x;
    int stride = gridDim.x * blockDim.x;
    for (int i = idx; i < N_NODES * HID; i += stride) g_agg[i] = 0.f;
    for (int i = idx; i < N_NODES; i += stride) g_cnt[i] = 0.f;
    if (idx < N_GRAPHS * HID) g_gsum[idx] = 0.f;
    if (idx < N_GRAPHS) g_gcnt[idx] = 0.f;
}

// ---------------- K1: edge messages ----------------
// msg[e, n] = sum_j h(e,j) * (x[src] @ W2_j)[n] + (x[src] @ B)[n]
// Per j: T = X_tile @ W2_j via fp16 m16n8k16 mma (A = x in fp16, fixed),
// K=32 in two k16 steps, then fp32 fold acc += h_row * T.
// Bias handled as final slab with h == 1.
//
// smem layout (half2 elements, u32 units), chunk = 4 j-slabs:
//   half2 pair (k, k+1), kk = k/2 in [0,16) per j, col n in [0,32):
//   off_u32 = j*512 + (kk&3)*128 + ((n<<2) ^ ((kk&3)<<3)) + (kk>>2)
// Consumer (lane r0=lane>>2, c0=lane&3) reads one uint4 per (jj, nb) at
//   jj*512 + c0*128 + ((n<<2) ^ (c0<<3)),  n = nb*8 + r0
// giving {b_k16s0_lo, b_k16s0_hi, b_k16s1_lo, b_k16s1_hi}; conflict-free.
__global__ void __launch_bounds__(256, 2) edge_kernel(
    const float* __restrict__ x, const int* __restrict__ ei,
    const float* __restrict__ ea,
    const float* __restrict__ w1g, const float* __restrict__ b1g,
    const float* __restrict__ w2, const float* __restrict__ b2)
{
    __shared__ unsigned w2_sm[2048];   // 8 KB chunk (4 j-slabs)
    __shared__ float w1_sm[64], b1_sm[64];

    const int tid  = threadIdx.x;
    const int lane = tid & 31;
    const int wrp  = tid >> 5;
    const int e0   = blockIdx.x * TILE_E;

    if (tid < 64) { w1_sm[tid] = w1g[tid]; b1_sm[tid] = b1g[tid]; }

    const int r0 = lane >> 2;      // 0..7
    const int c0 = lane & 3;       // 0..3

    int      dstv[4];
    bool     val[4];
    float    av[4];
    unsigned xh[4][4];             // fp16x2 A fragments (x only), fixed

    #pragma unroll
    for (int t = 0; t < 4; t++) {
        int eg = e0 + wrp * 32 + r0 + t * 8;
        val[t] = (eg < N_EDGES);
        int s  = val[t] ? ei[eg] : 0;
        dstv[t] = val[t] ? ei[N_EDGES + eg] : 0;
        av[t]   = val[t] ? ea[eg] : 0.f;
        const float2* xr2 = (const float2*)(x + s * IN_F);
        #pragma unroll
        for (int u = 0; u < 4; u++) {
            float2 f = xr2[c0 + 4 * u];          // cols 2c0+8u, 2c0+8u+1
            xh[t][u] = val[t] ? packh2(f.x, f.y) : 0u;
        }
    }

    // degree counts: exactly once per edge
    if (c0 == 0) {
        #pragma unroll
        for (int t = 0; t < 4; t++)
            if (val[t]) atomicAdd(&g_cnt[dstv[t]], 1.f);
    }

    int nsw[4];
    #pragma unroll
    for (int nb = 0; nb < 4; nb++)
        nsw[nb] = (((nb * 8 + r0) << 2) ^ (c0 << 3));
    const int cbase = c0 * 128;

    float acc[2][4][4];
    #pragma unroll
    for (int a = 0; a < 2; a++)
        #pragma unroll
        for (int b = 0; b < 4; b++)
            #pragma unroll
            for (int c = 0; c < 4; c++) acc[a][b][c] = 0.f;

    for (int jc = 0; jc < 17; jc++) {
        __syncthreads();
        if (jc < 16) {
            #pragma unroll
            for (int p = 0; p < 8; p++) {
                int f = tid + p * 256;            // half2 id, 0..2047
                int kk = f >> 5;                  // 0..63 (k-pair in chunk)
                int n  = f & 31;
                int kg = jc * 128 + 2 * kk;       // global k row
                float lo = w2[kg * 32 + n];
                float hi = w2[kg * 32 + 32 + n];
                int j = kk >> 4, kkl = kk & 15;
                int c0p = kkl & 3, w = kkl >> 2;
                w2_sm[j * 512 + c0p * 128 + (((n << 2) ^ (c0p << 3))) + w] =
                    packh2(lo, hi);
            }
        } else {
            // bias slab: 32 k-rows (j local 0)
            #pragma unroll
            for (int p = 0; p < 2; p++) {
                int f = tid + p * 256;            // 0..511
                int kk = f >> 5;                  // 0..15
                int n  = f & 31;
                float lo = b2[2 * kk * 32 + n];
                float hi = b2[(2 * kk + 1) * 32 + n];
                int c0p = kk & 3, w = kk >> 2;
                w2_sm[c0p * 128 + (((n << 2) ^ (c0p << 3))) + w] = packh2(lo, hi);
            }
        }
        __syncthreads();

        const int njj = (jc < 16) ? 4 : 1;
        for (int jj = 0; jj < njj; jj++) {
            float h[4];
            if (jc < 16) {
                int j = jc * 4 + jj;
                float wj = w1_sm[j], bj = b1_sm[j];
                #pragma unroll
                for (int t = 0; t < 4; t++)
                    h[t] = fmaxf(fmaf(av[t], wj, bj), 0.f);
            } else {
                h[0] = h[1] = h[2] = h[3] = 1.f;
            }
            const unsigned* sb = w2_sm + jj * 512 + cbase;
            #pragma unroll
            for (int nb = 0; nb < 4; nb++) {
                uint4 bq = *(const uint4*)(sb + nsw[nb]);
                float T0[4], T1[4];
                MMA16_SET(T0, xh[0][0], xh[1][0], xh[0][1], xh[1][1], bq.x, bq.y);
                MMA16_SET(T1, xh[2][0], xh[3][0], xh[2][1], xh[3][1], bq.x, bq.y);
                MMA16_ACC(T0, xh[0][2], xh[1][2], xh[0][3], xh[1][3], bq.z, bq.w);
                MMA16_ACC(T1, xh[2][2], xh[3][2], xh[2][3], xh[3][3], bq.z, bq.w);
                // fold: acc += h_row * T (T[0,1]: edge t even; T[2,3]: t odd)
                acc[0][nb][0] = fmaf(h[0], T0[0], acc[0][nb][0]);
                acc[0][nb][1] = fmaf(h[0], T0[1], acc[0][nb][1]);
                acc[0][nb][2] = fmaf(h[1], T0[2], acc[0][nb][2]);
                acc[0][nb][3] = fmaf(h[1], T0[3], acc[0][nb][3]);
                acc[1][nb][0] = fmaf(h[2], T1[0], acc[1][nb][0]);
                acc[1][nb][1] = fmaf(h[2], T1[1], acc[1][nb][1]);
                acc[1][nb][2] = fmaf(h[3], T1[2], acc[1][nb][2]);
                acc[1][nb][3] = fmaf(h[3], T1[3], acc[1][nb][3]);
            }
        }
    }

    // scatter messages (segment-sum by dst)
    #pragma unroll
    for (int tt = 0; tt < 2; tt++) {
        int t0 = tt * 2, t1 = tt * 2 + 1;
        #pragma unroll
        for (int nb = 0; nb < 4; nb++) {
            int n = nb * 8 + 2 * c0;
            if (val[t0]) {
                atomicAdd(&g_agg[dstv[t0] * HID + n],     acc[tt][nb][0]);
                atomicAdd(&g_agg[dstv[t0] * HID + n + 1], acc[tt][nb][1]);
            }
            if (val[t1]) {
                atomicAdd(&g_agg[dstv[t1] * HID + n],     acc[tt][nb][2]);
                atomicAdd(&g_agg[dstv[t1] * HID + n + 1], acc[tt][nb][3]);
            }
        }
    }
}

// ---------------- K2: node update + graph pooling ----------------
__global__ void __launch_bounds__(256) node_kernel(
    const float* __restrict__ x, const int* __restrict__ batch,
    const float* __restrict__ root, const float* __restrict__ conv_bias)
{
    int wrp = threadIdx.x >> 5, lane = threadIdx.x & 31;
    int n = blockIdx.x * 8 + wrp;
    if (n >= N_NODES) return;
    float v = g_agg[n * HID + lane];
    float c = g_cnt[n];
    v /= fmaxf(c, 1.f);
    float xv = x[n * IN_F + lane];
    float s = 0.f;
    #pragma unroll
    for (int i = 0; i < IN_F; i++) {
        float xi = __shfl_sync(0xffffffffu, xv, i);
        s = fmaf(xi, root[i * HID + lane], s);
    }
    v = fmaxf(v + s + conv_bias[lane], 0.f);
    int g = batch[n];
    atomicAdd(&g_gsum[g * HID + lane], v);
    if (lane == 0) atomicAdd(&g_gcnt[g], 1.f);
}

// ---------------- K3: classifier ----------------
__global__ void final_kernel(const float* __restrict__ lin_w,
                             const float* __restrict__ lin_b,
                             float* __restrict__ out)
{
    int t = threadIdx.x;
    if (t >= N_GRAPHS * 2) return;
    int g = t >> 1, c = t & 1;
    float cnt = fmaxf(g_gcnt[g], 1.f);
    float s = 0.f;
    #pragma unroll
    for (int h = 0; h < HID; h++)
        s += g_gsum[g * HID + h] * lin_w[h * 2 + c];
    out[g * 2 + c] = s / cnt + lin_b[c];
}

// ---------------- launcher ----------------
extern "C" void kernel_launch(void* const* d_in, const int* in_sizes, int n_in,
                              void* d_out, int out_size) {
    const float* x    = (const float*)d_in[0];
    const int*   ei   = (const int*)  d_in[1];
    const float* ea   = (const float*)d_in[2];
    const int*   bat  = (const int*)  d_in[3];
    const float* w1   = (const float*)d_in[4];
    const float* b1   = (const float*)d_in[5];
    const float* w2   = (const float*)d_in[6];
    const float* b2   = (const float*)d_in[7];
    const float* root = (const float*)d_in[8];
    const float* cb   = (const float*)d_in[9];
    const float* lw   = (const float*)d_in[10];
    const float* lb   = (const float*)d_in[11];
    float* out = (float*)d_out;

    zero_kernel<<<512, 256>>>();
    edge_kernel<<<(N_EDGES + TILE_E - 1) / TILE_E, 256>>>(x, ei, ea, w1, b1, w2, b2);
    node_kernel<<<(N_NODES + 7) / 8, 256>>>(x, bat, root, cb);
    final_kernel<<<1, 128>>>(lw, lb, out);
}